// round 15
// baseline (speedup 1.0000x reference)
#include <cuda_runtime.h>
#include <cuda_fp16.h>
#include <stdint.h>
#include <math.h>
#include <string.h>

// Problem constants
#define N_ROWS 65536      // B*H*W = 16*64*64
#define N_CODES 2048
#define CDIM 64
#define BM 128
#define N_TILES (N_ROWS / BM)      // 512
#define E_TILES (N_CODES / BM)     // 16
#define NCHUNK 16                  // 128-code chunks

// Output layout: concat(z_q_out[B,C,H,W], loss, perplexity, indices) as fp32
#define O_LOSS 4194304
#define O_PERP 4194305
#define O_IDX  4194306

// smem geometry: plain row-major fp16 rows (128B data) padded to 144B so
// ldmatrix 8-row phases hit distinct 4-bank groups.
#define ROWB 144
#define PLANE_A (128 * ROWB)        // 18432 B
#define PLANE_B (128 * ROWB)        // 18432 B (128-code chunk)
#define A_BYTES (2 * PLANE_A)       // 36864 (2 fp16 planes)
#define DSMEM_REQ (A_BYTES + 4 * PLANE_B)   // 110592 -> 2 CTAs/SM

// ---------------- scratch (device globals; no allocations allowed) --------
__device__ int   g_counts[N_CODES];
__device__ float g_sumsq;

// fp16 split planes, dense row-major: uint4 index = row*8 + kgroup
__device__ uint4 g_z0[N_TILES * 1024];
__device__ uint4 g_z1[N_TILES * 1024];
__device__ uint4 g_e0[E_TILES * 1024];
__device__ uint4 g_e1[E_TILES * 1024];

// ---------------- helpers -------------------------------------------------
__device__ __forceinline__ uint32_t smem_u32(const void* p) {
    uint32_t a;
    asm("{ .reg .u64 t; cvta.to.shared.u64 t, %1; cvt.u32.u64 %0, t; }"
        : "=r"(a) : "l"(p));
    return a;
}

__device__ __forceinline__ void cp16(uint32_t dst, const void* src) {
    asm volatile("cp.async.cg.shared.global [%0], [%1], 16;"
                 :: "r"(dst), "l"(src) : "memory");
}
#define CP_COMMIT() asm volatile("cp.async.commit_group;" ::: "memory")
#define CP_WAIT1()  asm volatile("cp.async.wait_group 1;" ::: "memory")
#define CP_WAIT0()  asm volatile("cp.async.wait_group 0;" ::: "memory")

__device__ __forceinline__ void ldm4(uint32_t* r, uint32_t addr) {
    asm volatile("ldmatrix.sync.aligned.m8n8.x4.shared.b16 {%0,%1,%2,%3}, [%4];"
                 : "=r"(r[0]), "=r"(r[1]), "=r"(r[2]), "=r"(r[3]) : "r"(addr));
}

#define MMA16816(cc, a0, a1, a2, a3, bb0, bb1) \
    asm("mma.sync.aligned.m16n8k16.row.col.f32.f16.f16.f32 " \
        "{%0,%1,%2,%3}, {%4,%5,%6,%7}, {%8,%9}, {%0,%1,%2,%3};" \
        : "+f"((cc)[0]), "+f"((cc)[1]), "+f"((cc)[2]), "+f"((cc)[3]) \
        : "r"(a0), "r"(a1), "r"(a2), "r"(a3), "r"(bb0), "r"(bb1))

// ---------------- fp16 double split --------------------------------------
__device__ __forceinline__ void split2(float v, unsigned short& u0,
                                       unsigned short& u1) {
    __half h0 = __float2half_rn(v);
    float r1 = v - __half2float(h0);
    __half h1 = __float2half_rn(r1);
    memcpy(&u0, &h0, 2); memcpy(&u1, &h1, 2);
}
__device__ __forceinline__ uint32_t pack2(unsigned short lo, unsigned short hi) {
    return (uint32_t)lo | ((uint32_t)hi << 16);
}

// ---------------- kernel: split z (plain row-major) ----------------------
__global__ void __launch_bounds__(128)
vq_split_z(const float* __restrict__ z) {
    __shared__ float s[64][129];
    const int tile = blockIdx.x;
    const int n0 = tile * BM;
    const int b = n0 >> 12, p0 = n0 & 4095;
    const float* src = z + ((size_t)b * CDIM) * 4096 + p0;
    const int i = threadIdx.x;
#pragma unroll 8
    for (int c = 0; c < 64; c++) s[c][i] = src[(size_t)c * 4096 + i];
    __syncthreads();

#pragma unroll
    for (int j = 0; j < 8; j++) {
        unsigned short u0[8], u1[8];
#pragma unroll
        for (int q = 0; q < 8; q++) split2(s[j * 8 + q][i], u0[q], u1[q]);
        int idx = tile * 1024 + i * 8 + j;
        g_z0[idx] = make_uint4(pack2(u0[0], u0[1]), pack2(u0[2], u0[3]),
                               pack2(u0[4], u0[5]), pack2(u0[6], u0[7]));
        g_z1[idx] = make_uint4(pack2(u1[0], u1[1]), pack2(u1[2], u1[3]),
                               pack2(u1[4], u1[5]), pack2(u1[6], u1[7]));
    }
}

// ---------------- kernel: split codebook (plain row-major) ---------------
__global__ void __launch_bounds__(128)
vq_split_cb(const float* __restrict__ cb) {
    const int tile = blockIdx.x;
    const int i = threadIdx.x;
    float v[64];
    const float4* src = (const float4*)(cb + (size_t)(tile * BM + i) * CDIM);
#pragma unroll
    for (int t = 0; t < 16; t++) {
        float4 x = src[t];
        v[t * 4] = x.x; v[t * 4 + 1] = x.y; v[t * 4 + 2] = x.z; v[t * 4 + 3] = x.w;
    }
#pragma unroll
    for (int j = 0; j < 8; j++) {
        unsigned short u0[8], u1[8];
#pragma unroll
        for (int q = 0; q < 8; q++) split2(v[j * 8 + q], u0[q], u1[q]);
        int idx = tile * 1024 + i * 8 + j;
        g_e0[idx] = make_uint4(pack2(u0[0], u0[1]), pack2(u0[2], u0[3]),
                               pack2(u0[4], u0[5]), pack2(u0[6], u0[7]));
        g_e1[idx] = make_uint4(pack2(u1[0], u1[1]), pack2(u1[2], u1[3]),
                               pack2(u1[4], u1[5]), pack2(u1[6], u1[7]));
    }
}

__global__ void vq_init() {
    for (int i = threadIdx.x; i < N_CODES; i += blockDim.x) g_counts[i] = 0;
    if (threadIdx.x == 0) g_sumsq = 0.0f;
}

// ---------------- kernel: mma.sync GEMM + argmax + fused epilogue --------
// Emulated fp32 via fp16x2: logits = h0e0+h0e1+h1e0+h1e1. 8 warps of 256
// threads, warp tile 64x32, 128-code chunks (16), 2 CTAs/SM.
// Per ks-step: 12 ldm4 : 64 HMMA.
__global__ void __launch_bounds__(256, 2)
vq_mma(const float* __restrict__ cbf, float* __restrict__ out) {
    extern __shared__ char dsm[];
    const int tid = threadIdx.x;
    const int w = tid >> 5, lane = tid & 31;
    const int g = lane >> 2, q = lane & 3;
    const int mrow = lane & 7, quad = lane >> 3;
    const int wm = (w & 1) * 64, wn = (w >> 1) * 32;
    const int tile = blockIdx.x;

    const uint32_t sA = smem_u32(dsm);
    const uint32_t sB = sA + A_BYTES;

    // ldmatrix per-thread intra-plane offsets
    const uint32_t aoff = (uint32_t)(wm + mrow + 8 * (quad & 1)) * ROWB
                        + 16 * (quad >> 1);
    const uint32_t boff = (uint32_t)(wn + mrow + 8 * (quad >> 1)) * ROWB
                        + 16 * (quad & 1);

    // prologue: A tiles (2 planes) + B chunk 0 (one commit group)
    {
        const uint4* zs[2] = {g_z0 + tile * 1024, g_z1 + tile * 1024};
        for (int t = tid; t < 2048; t += 256) {
            int pl = t >> 10, rem = t & 1023, r = rem >> 3, j = rem & 7;
            cp16(sA + pl * PLANE_A + r * ROWB + j * 16, zs[pl] + rem);
        }
        const uint4* es[2] = {g_e0, g_e1};
        for (int t = tid; t < 2048; t += 256) {
            int pl = t >> 10, rem = t & 1023, r = rem >> 3, j = rem & 7;
            cp16(sB + pl * PLANE_B + r * ROWB + j * 16, es[pl] + rem);
        }
        CP_COMMIT();
    }

    float bv[8];
    int   bi[8];
#pragma unroll
    for (int e = 0; e < 8; e++) { bv[e] = -3.4e38f; bi[e] = 0; }

    for (int ch = 0; ch < NCHUNK; ch++) {
        if (ch < NCHUNK - 1) {   // prefetch next B chunk into other buffer
            const uint4* es[2] = {g_e0 + (ch + 1) * 1024, g_e1 + (ch + 1) * 1024};
            uint32_t dstb = sB + ((ch + 1) & 1) * (2 * PLANE_B);
            for (int t = tid; t < 2048; t += 256) {
                int pl = t >> 10, rem = t & 1023, r = rem >> 3, j = rem & 7;
                cp16(dstb + pl * PLANE_B + r * ROWB + j * 16, es[pl] + rem);
            }
            CP_COMMIT();
            CP_WAIT1();
        } else {
            CP_WAIT0();
        }
        __syncthreads();

        const uint32_t bB = sB + (ch & 1) * (2 * PLANE_B);

        float c[4][4][4];
#pragma unroll
        for (int mi = 0; mi < 4; mi++)
#pragma unroll
            for (int ni = 0; ni < 4; ni++)
#pragma unroll
                for (int e = 0; e < 4; e++) c[mi][ni][e] = 0.0f;

#pragma unroll
        for (int ks = 0; ks < 4; ks++) {
            const uint32_t koff = ks * 32;
            uint32_t B0[8], B1[8];
            ldm4(B0,     bB + 0 * PLANE_B + boff + koff);
            ldm4(B0 + 4, bB + 0 * PLANE_B + boff + koff + 16 * ROWB);
            ldm4(B1,     bB + 1 * PLANE_B + boff + koff);
            ldm4(B1 + 4, bB + 1 * PLANE_B + boff + koff + 16 * ROWB);

            uint32_t A[16];
            // h0: products with e0, e1 (interleaved per (mi,ni))
            ldm4(A,      sA + 0 * PLANE_A + aoff + koff);
            ldm4(A + 4,  sA + 0 * PLANE_A + aoff + koff + 16 * ROWB);
            ldm4(A + 8,  sA + 0 * PLANE_A + aoff + koff + 32 * ROWB);
            ldm4(A + 12, sA + 0 * PLANE_A + aoff + koff + 48 * ROWB);
#pragma unroll
            for (int mi = 0; mi < 4; mi++)
#pragma unroll
                for (int ni = 0; ni < 4; ni++) {
                    MMA16816(c[mi][ni], A[mi*4], A[mi*4+1], A[mi*4+2], A[mi*4+3],
                             B0[ni*2], B0[ni*2+1]);
                    MMA16816(c[mi][ni], A[mi*4], A[mi*4+1], A[mi*4+2], A[mi*4+3],
                             B1[ni*2], B1[ni*2+1]);
                }
            // h1: products with e0, e1
            ldm4(A,      sA + 1 * PLANE_A + aoff + koff);
            ldm4(A + 4,  sA + 1 * PLANE_A + aoff + koff + 16 * ROWB);
            ldm4(A + 8,  sA + 1 * PLANE_A + aoff + koff + 32 * ROWB);
            ldm4(A + 12, sA + 1 * PLANE_A + aoff + koff + 48 * ROWB);
#pragma unroll
            for (int mi = 0; mi < 4; mi++)
#pragma unroll
                for (int ni = 0; ni < 4; ni++) {
                    MMA16816(c[mi][ni], A[mi*4], A[mi*4+1], A[mi*4+2], A[mi*4+3],
                             B0[ni*2], B0[ni*2+1]);
                    MMA16816(c[mi][ni], A[mi*4], A[mi*4+1], A[mi*4+2], A[mi*4+3],
                             B1[ni*2], B1[ni*2+1]);
                }
        }

        // fold chunk into running argmax (ascending candidate order -> strict >)
        const int cb0 = ch * 128 + wn + 2 * q;
#pragma unroll
        for (int mi = 0; mi < 4; mi++) {
            const int lo = mi * 2, hi = mi * 2 + 1;
#pragma unroll
            for (int ni = 0; ni < 4; ni++) {
                int ce = cb0 + 8 * ni;
                if (c[mi][ni][0] > bv[lo]) { bv[lo] = c[mi][ni][0]; bi[lo] = ce; }
                if (c[mi][ni][1] > bv[lo]) { bv[lo] = c[mi][ni][1]; bi[lo] = ce + 1; }
                if (c[mi][ni][2] > bv[hi]) { bv[hi] = c[mi][ni][2]; bi[hi] = ce; }
                if (c[mi][ni][3] > bv[hi]) { bv[hi] = c[mi][ni][3]; bi[hi] = ce + 1; }
            }
        }
        __syncthreads();
    }

    // quad shuffle reduce (lanes sharing a row differ only in q)
#pragma unroll
    for (int e = 0; e < 8; e++) {
#pragma unroll
        for (int off = 1; off <= 2; off <<= 1) {
            float ov = __shfl_xor_sync(0xffffffffu, bv[e], off);
            int   oi = __shfl_xor_sync(0xffffffffu, bi[e], off);
            if (ov > bv[e] || (ov == bv[e] && oi < bi[e])) { bv[e] = ov; bi[e] = oi; }
        }
    }

    // reductions staged in dead B region (A planes still needed for zp)
    float* sval = (float*)(dsm + A_BYTES);             // [128][4]
    int*   sidx = (int*)(dsm + A_BYTES + 2048);        // [128][4]
    int*   ids  = (int*)(dsm + A_BYTES + 4096);        // [128]
    float* wsum = (float*)(dsm + A_BYTES + 4608);      // [8]
    float* zq   = (float*)(dsm + A_BYTES + 4672);      // [128][65]
    if (q == 0) {
#pragma unroll
        for (int e = 0; e < 8; e++) {
            int r = wm + 16 * (e >> 1) + 8 * (e & 1) + g;
            sval[r * 4 + (w >> 1)] = bv[e];
            sidx[r * 4 + (w >> 1)] = bi[e];
        }
    }
    __syncthreads();
    if (tid < 128) {
        float v = sval[tid * 4];
        int   i2 = sidx[tid * 4];
#pragma unroll
        for (int wg = 1; wg < 4; wg++) {
            float ov = sval[tid * 4 + wg];
            int   oi = sidx[tid * 4 + wg];
            if (ov > v || (ov == v && oi < i2)) { v = ov; i2 = oi; }
        }
        int n = tile * BM + tid;
        ids[tid] = i2;
        out[O_IDX + n] = (float)i2;
        atomicAdd(&g_counts[i2], 1);
    }
    __syncthreads();

    // gather codebook rows (fp32, L2-resident) into staging
    {
        int row = tid >> 1, h = tid & 1;
        const float4* src = (const float4*)(cbf + (size_t)ids[row] * CDIM + h * 32);
#pragma unroll
        for (int t = 0; t < 8; t++) {
            float4 vv = src[t];
            int c = h * 32 + t * 4;
            zq[row * 65 + c]     = vv.x;
            zq[row * 65 + c + 1] = vv.y;
            zq[row * 65 + c + 2] = vv.z;
            zq[row * 65 + c + 3] = vv.w;
        }
    }
    __syncthreads();

    // loss + transposed coalesced z_q store; zp = h0+h1 from smem planes
    {
        const int i = tid & 127;
        const int c0 = tid >> 7;          // 0..1
        const int b  = tile >> 5;
        const int p0 = (tile & 31) * BM;
        float* od = out + ((size_t)b * CDIM) * 4096 + p0;
        const char* a0 = dsm + 0 * PLANE_A + i * ROWB;
        const char* a1 = dsm + 1 * PLANE_A + i * ROWB;
        float lsum = 0.0f;
#pragma unroll
        for (int s = 0; s < 32; s++) {
            int c = c0 + 2 * s;
            float zp = __half2float(*(const __half*)(a0 + 2 * c))
                     + __half2float(*(const __half*)(a1 + 2 * c));
            float vq = zq[i * 65 + c];
            float d = vq - zp;
            lsum += d * d;
            od[(size_t)c * 4096 + i] = vq;
        }
        for (int o = 16; o > 0; o >>= 1)
            lsum += __shfl_down_sync(0xffffffffu, lsum, o);
        if (lane == 0) wsum[w] = lsum;
        __syncthreads();
        if (tid == 0) {
            float t = 0.0f;
#pragma unroll
            for (int ww = 0; ww < 8; ww++) t += wsum[ww];
            atomicAdd(&g_sumsq, t);
        }
    }
}

// ---------------- kernel: scalars ----------------------------------------
__global__ void vq_final(float* __restrict__ out) {
    __shared__ float red[256];
    const int tid = threadIdx.x;
    float h = 0.0f;
    for (int i = tid; i < N_CODES; i += 256) {
        float e = (float)g_counts[i] * (1.0f / 65536.0f);
        h -= e * logf(e + 1e-10f);
    }
    red[tid] = h;
    __syncthreads();
    for (int o = 128; o > 0; o >>= 1) {
        if (tid < o) red[tid] += red[tid + o];
        __syncthreads();
    }
    if (tid == 0) {
        out[O_LOSS] = 1.25f * g_sumsq / 4194304.0f;
        out[O_PERP] = expf(red[0]);
    }
}

extern "C" void kernel_launch(void* const* d_in, const int* in_sizes, int n_in,
                              void* d_out, int out_size) {
    const float* z  = (const float*)d_in[0];
    const float* cb = (const float*)d_in[1];
    if (n_in >= 2 && in_sizes[0] == N_CODES * CDIM) {
        z  = (const float*)d_in[1];
        cb = (const float*)d_in[0];
    }
    float* out = (float*)d_out;

    cudaFuncSetAttribute(vq_mma, cudaFuncAttributeMaxDynamicSharedMemorySize,
                         DSMEM_REQ);

    vq_split_z<<<N_TILES, 128>>>(z);
    vq_split_cb<<<E_TILES, 128>>>(cb);
    vq_init<<<1, 256>>>();
    vq_mma<<<N_TILES, 256, DSMEM_REQ>>>(cb, out);
    vq_final<<<1, 256>>>(out);
    (void)out_size;
}

// round 17
// speedup vs baseline: 1.0751x; 1.0751x over previous
#include <cuda_runtime.h>
#include <cuda_fp16.h>
#include <stdint.h>
#include <math.h>
#include <string.h>

// Problem constants
#define N_ROWS 65536      // B*H*W = 16*64*64
#define N_CODES 2048
#define CDIM 64
#define BM 128
#define N_TILES (N_ROWS / BM)      // 512

// Output layout: concat(z_q_out[B,C,H,W], loss, perplexity, indices) as fp32
#define O_LOSS 4194304
#define O_PERP 4194305
#define O_IDX  4194306

// smem: A planes only (row-major fp16, 128B rows padded to 144B) + staging
#define ROWB 144
#define PLANE_A (128 * ROWB)        // 18432 B
#define A_BYTES (2 * PLANE_A)       // 36864
#define DSMEM_REQ (A_BYTES + 38016) // A + epilogue staging

// ---------------- scratch (device globals; no allocations allowed) --------
__device__ int   g_counts[N_CODES];
__device__ float g_sumsq;

// fp16 split planes of z, dense row-major: uint4 index = row*8 + kgroup
__device__ uint4 g_z0[N_TILES * 1024];
__device__ uint4 g_z1[N_TILES * 1024];
// codebook planes in FRAGMENT-MAJOR layout (B operand register image):
// index = (((pl*64 + ct)*4 + ks)*2 + h)*32 + lane,  ct = 32-code block.
__device__ uint4 g_bf[2 * 64 * 4 * 2 * 32];

// ---------------- helpers -------------------------------------------------
__device__ __forceinline__ uint32_t smem_u32(const void* p) {
    uint32_t a;
    asm("{ .reg .u64 t; cvta.to.shared.u64 t, %1; cvt.u32.u64 %0, t; }"
        : "=r"(a) : "l"(p));
    return a;
}

__device__ __forceinline__ void cp16(uint32_t dst, const void* src) {
    asm volatile("cp.async.cg.shared.global [%0], [%1], 16;"
                 :: "r"(dst), "l"(src) : "memory");
}
#define CP_COMMIT() asm volatile("cp.async.commit_group;" ::: "memory")
#define CP_WAIT0()  asm volatile("cp.async.wait_group 0;" ::: "memory")

__device__ __forceinline__ void ldm4(uint32_t* r, uint32_t addr) {
    asm volatile("ldmatrix.sync.aligned.m8n8.x4.shared.b16 {%0,%1,%2,%3}, [%4];"
                 : "=r"(r[0]), "=r"(r[1]), "=r"(r[2]), "=r"(r[3]) : "r"(addr));
}

#define MMA16816(cc, a0, a1, a2, a3, bb0, bb1) \
    asm("mma.sync.aligned.m16n8k16.row.col.f32.f16.f16.f32 " \
        "{%0,%1,%2,%3}, {%4,%5,%6,%7}, {%8,%9}, {%0,%1,%2,%3};" \
        : "+f"((cc)[0]), "+f"((cc)[1]), "+f"((cc)[2]), "+f"((cc)[3]) \
        : "r"(a0), "r"(a1), "r"(a2), "r"(a3), "r"(bb0), "r"(bb1))

// ---------------- fp16 double split --------------------------------------
__device__ __forceinline__ void split2(float v, unsigned short& u0,
                                       unsigned short& u1) {
    __half h0 = __float2half_rn(v);
    float r1 = v - __half2float(h0);
    __half h1 = __float2half_rn(r1);
    memcpy(&u0, &h0, 2); memcpy(&u1, &h1, 2);
}
__device__ __forceinline__ uint32_t pack2(unsigned short lo, unsigned short hi) {
    return (uint32_t)lo | ((uint32_t)hi << 16);
}

// ---------------- kernel: split z (plain row-major planes) ---------------
__global__ void __launch_bounds__(128)
vq_split_z(const float* __restrict__ z) {
    __shared__ float s[64][129];
    const int tile = blockIdx.x;
    const int n0 = tile * BM;
    const int b = n0 >> 12, p0 = n0 & 4095;
    const float* src = z + ((size_t)b * CDIM) * 4096 + p0;
    const int i = threadIdx.x;
#pragma unroll 8
    for (int c = 0; c < 64; c++) s[c][i] = src[(size_t)c * 4096 + i];
    __syncthreads();

#pragma unroll
    for (int j = 0; j < 8; j++) {
        unsigned short u0[8], u1[8];
#pragma unroll
        for (int q = 0; q < 8; q++) split2(s[j * 8 + q][i], u0[q], u1[q]);
        int idx = tile * 1024 + i * 8 + j;
        g_z0[idx] = make_uint4(pack2(u0[0], u0[1]), pack2(u0[2], u0[3]),
                               pack2(u0[4], u0[5]), pack2(u0[6], u0[7]));
        g_z1[idx] = make_uint4(pack2(u1[0], u1[1]), pack2(u1[2], u1[3]),
                               pack2(u1[4], u1[5]), pack2(u1[6], u1[7]));
    }
}

// ---------------- kernel: split codebook -> fragment-major ---------------
// Replicates the ldmatrix.x4 register image: tile j, thread t holds
// [row t/4][halves 2(t%4), +1]. uint4 (pl,ct,ks,h,t):
//   r0 = e[c][kb..kb+1], r1 = e[c][kb+8..9], r2 = e[c+8][kb..], r3 = e[c+8][kb+8..]
// with c = ct*32 + h*16 + t/4, kb = ks*16 + 2*(t&3).
__global__ void __launch_bounds__(128)
vq_split_cb(const float* __restrict__ cb) {
    const int ct = blockIdx.x;          // 0..63
    const int ks = threadIdx.x >> 5;    // 0..3
    const int t  = threadIdx.x & 31;
    const int kb = ks * 16 + 2 * (t & 3);
#pragma unroll
    for (int h = 0; h < 2; h++) {
        int c = ct * 32 + h * 16 + (t >> 2);
        float v[8] = {
            cb[(size_t)c * 64 + kb],       cb[(size_t)c * 64 + kb + 1],
            cb[(size_t)c * 64 + kb + 8],   cb[(size_t)c * 64 + kb + 9],
            cb[(size_t)(c + 8) * 64 + kb],     cb[(size_t)(c + 8) * 64 + kb + 1],
            cb[(size_t)(c + 8) * 64 + kb + 8], cb[(size_t)(c + 8) * 64 + kb + 9]
        };
        unsigned short p0[8], p1[8];
#pragma unroll
        for (int j = 0; j < 8; j++) split2(v[j], p0[j], p1[j]);
        int base = ((ct * 4 + ks) * 2 + h) * 32 + t;
        g_bf[base] = make_uint4(pack2(p0[0], p0[1]), pack2(p0[2], p0[3]),
                                pack2(p0[4], p0[5]), pack2(p0[6], p0[7]));
        g_bf[16384 + base] = make_uint4(pack2(p1[0], p1[1]), pack2(p1[2], p1[3]),
                                        pack2(p1[4], p1[5]), pack2(p1[6], p1[7]));
    }
}

__global__ void vq_init() {
    for (int i = threadIdx.x; i < N_CODES; i += blockDim.x) g_counts[i] = 0;
    if (threadIdx.x == 0) g_sumsq = 0.0f;
}

// ---------------- kernel: mma.sync GEMM + argmax + fused epilogue --------
// fp16x2 emulated fp32: logits = h0e0+h0e1+h1e0+h1e1. 8 warps, warp tile
// 64x32, 2 CTAs/SM. B fragments streamed from L2 in fragment-major layout:
// ZERO __syncthreads in the mainloop (A smem is read-only after prologue).
__global__ void __launch_bounds__(256, 2)
vq_mma(const float* __restrict__ cbf, float* __restrict__ out) {
    extern __shared__ char dsm[];
    const int tid = threadIdx.x;
    const int w = tid >> 5, lane = tid & 31;
    const int g = lane >> 2, q = lane & 3;
    const int mrow = lane & 7, quad = lane >> 3;
    const int wm = (w & 1) * 64;
    const int wn_ct = w >> 1;           // which 32-code subblock (0..3)
    const int tile = blockIdx.x;

    const uint32_t sA = smem_u32(dsm);

    // ldmatrix per-thread intra-plane offset for A
    const uint32_t aoff = (uint32_t)(wm + mrow + 8 * (quad & 1)) * ROWB
                        + 16 * (quad >> 1);

    // prologue: A tiles (2 planes) via cp.async, one barrier total
    {
        const uint4* zs[2] = {g_z0 + tile * 1024, g_z1 + tile * 1024};
        for (int t = tid; t < 2048; t += 256) {
            int pl = t >> 10, rem = t & 1023, r = rem >> 3, j = rem & 7;
            cp16(sA + pl * PLANE_A + r * ROWB + j * 16, zs[pl] + rem);
        }
        CP_COMMIT();
    }
    CP_WAIT0();
    __syncthreads();

    float bv[8];
    int   bi[8];
#pragma unroll
    for (int e = 0; e < 8; e++) { bv[e] = -3.4e38f; bi[e] = 0; }

    for (int it = 0; it < 16; it++) {
        const int ct = it * 4 + wn_ct;

        float c[4][4][4];
#pragma unroll
        for (int mi = 0; mi < 4; mi++)
#pragma unroll
            for (int ni = 0; ni < 4; ni++)
#pragma unroll
                for (int e = 0; e < 4; e++) c[mi][ni][e] = 0.0f;

#pragma unroll
        for (int ks = 0; ks < 4; ks++) {
            // B fragments from L2, fragment-major -> coalesced LDG.128
            const uint4* bp = g_bf + (ct * 4 + ks) * 64 + lane;
            uint4 b00 = bp[0];            // plane0, codes ct*32+0..15
            uint4 b01 = bp[32];           // plane0, codes ct*32+16..31
            uint4 b10 = bp[16384];        // plane1, codes +0..15
            uint4 b11 = bp[16384 + 32];   // plane1, codes +16..31
            uint32_t B0[8] = {b00.x, b00.y, b00.z, b00.w,
                              b01.x, b01.y, b01.z, b01.w};
            uint32_t B1[8] = {b10.x, b10.y, b10.z, b10.w,
                              b11.x, b11.y, b11.z, b11.w};

            const uint32_t koff = ks * 32;
            uint32_t A[16];
            // h0 A-plane: products with e0, e1
            ldm4(A,      sA + 0 * PLANE_A + aoff + koff);
            ldm4(A + 4,  sA + 0 * PLANE_A + aoff + koff + 16 * ROWB);
            ldm4(A + 8,  sA + 0 * PLANE_A + aoff + koff + 32 * ROWB);
            ldm4(A + 12, sA + 0 * PLANE_A + aoff + koff + 48 * ROWB);
#pragma unroll
            for (int mi = 0; mi < 4; mi++)
#pragma unroll
                for (int ni = 0; ni < 4; ni++) {
                    MMA16816(c[mi][ni], A[mi*4], A[mi*4+1], A[mi*4+2], A[mi*4+3],
                             B0[ni*2], B0[ni*2+1]);
                    MMA16816(c[mi][ni], A[mi*4], A[mi*4+1], A[mi*4+2], A[mi*4+3],
                             B1[ni*2], B1[ni*2+1]);
                }
            // h1 A-plane: products with e0, e1
            ldm4(A,      sA + 1 * PLANE_A + aoff + koff);
            ldm4(A + 4,  sA + 1 * PLANE_A + aoff + koff + 16 * ROWB);
            ldm4(A + 8,  sA + 1 * PLANE_A + aoff + koff + 32 * ROWB);
            ldm4(A + 12, sA + 1 * PLANE_A + aoff + koff + 48 * ROWB);
#pragma unroll
            for (int mi = 0; mi < 4; mi++)
#pragma unroll
                for (int ni = 0; ni < 4; ni++) {
                    MMA16816(c[mi][ni], A[mi*4], A[mi*4+1], A[mi*4+2], A[mi*4+3],
                             B0[ni*2], B0[ni*2+1]);
                    MMA16816(c[mi][ni], A[mi*4], A[mi*4+1], A[mi*4+2], A[mi*4+3],
                             B1[ni*2], B1[ni*2+1]);
                }
        }

        // fold into running argmax (ascending candidate order -> strict >)
        const int cb0 = ct * 32 + 2 * q;
#pragma unroll
        for (int mi = 0; mi < 4; mi++) {
            const int lo = mi * 2, hi = mi * 2 + 1;
#pragma unroll
            for (int ni = 0; ni < 4; ni++) {
                int ce = cb0 + 8 * ni;
                if (c[mi][ni][0] > bv[lo]) { bv[lo] = c[mi][ni][0]; bi[lo] = ce; }
                if (c[mi][ni][1] > bv[lo]) { bv[lo] = c[mi][ni][1]; bi[lo] = ce + 1; }
                if (c[mi][ni][2] > bv[hi]) { bv[hi] = c[mi][ni][2]; bi[hi] = ce; }
                if (c[mi][ni][3] > bv[hi]) { bv[hi] = c[mi][ni][3]; bi[hi] = ce + 1; }
            }
        }
    }

    // quad shuffle reduce (lanes sharing a row differ only in q)
#pragma unroll
    for (int e = 0; e < 8; e++) {
#pragma unroll
        for (int off = 1; off <= 2; off <<= 1) {
            float ov = __shfl_xor_sync(0xffffffffu, bv[e], off);
            int   oi = __shfl_xor_sync(0xffffffffu, bi[e], off);
            if (ov > bv[e] || (ov == bv[e] && oi < bi[e])) { bv[e] = ov; bi[e] = oi; }
        }
    }

    // reductions staged after A region (A planes still needed for zp)
    float* sval = (float*)(dsm + A_BYTES);             // [128][4]
    int*   sidx = (int*)(dsm + A_BYTES + 2048);        // [128][4]
    int*   ids  = (int*)(dsm + A_BYTES + 4096);        // [128]
    float* wsum = (float*)(dsm + A_BYTES + 4608);      // [8]
    float* zq   = (float*)(dsm + A_BYTES + 4672);      // [128][65]
    if (q == 0) {
#pragma unroll
        for (int e = 0; e < 8; e++) {
            int r = wm + 16 * (e >> 1) + 8 * (e & 1) + g;
            sval[r * 4 + (w >> 1)] = bv[e];
            sidx[r * 4 + (w >> 1)] = bi[e];
        }
    }
    __syncthreads();
    if (tid < 128) {
        float v = sval[tid * 4];
        int   i2 = sidx[tid * 4];
#pragma unroll
        for (int wg = 1; wg < 4; wg++) {
            float ov = sval[tid * 4 + wg];
            int   oi = sidx[tid * 4 + wg];
            if (ov > v || (ov == v && oi < i2)) { v = ov; i2 = oi; }
        }
        int n = tile * BM + tid;
        ids[tid] = i2;
        out[O_IDX + n] = (float)i2;
        atomicAdd(&g_counts[i2], 1);
    }
    __syncthreads();

    // gather codebook rows (fp32, L2-resident) into staging
    {
        int row = tid >> 1, h = tid & 1;
        const float4* src = (const float4*)(cbf + (size_t)ids[row] * CDIM + h * 32);
#pragma unroll
        for (int t = 0; t < 8; t++) {
            float4 vv = src[t];
            int c = h * 32 + t * 4;
            zq[row * 65 + c]     = vv.x;
            zq[row * 65 + c + 1] = vv.y;
            zq[row * 65 + c + 2] = vv.z;
            zq[row * 65 + c + 3] = vv.w;
        }
    }
    __syncthreads();

    // loss + transposed coalesced z_q store; zp = h0+h1 from smem planes
    {
        const int i = tid & 127;
        const int c0 = tid >> 7;          // 0..1
        const int b  = tile >> 5;
        const int p0 = (tile & 31) * BM;
        float* od = out + ((size_t)b * CDIM) * 4096 + p0;
        const char* a0 = dsm + 0 * PLANE_A + i * ROWB;
        const char* a1 = dsm + 1 * PLANE_A + i * ROWB;
        float lsum = 0.0f;
#pragma unroll
        for (int s = 0; s < 32; s++) {
            int c = c0 + 2 * s;
            float zp = __half2float(*(const __half*)(a0 + 2 * c))
                     + __half2float(*(const __half*)(a1 + 2 * c));
            float vq = zq[i * 65 + c];
            float d = vq - zp;
            lsum += d * d;
            od[(size_t)c * 4096 + i] = vq;
        }
        for (int o = 16; o > 0; o >>= 1)
            lsum += __shfl_down_sync(0xffffffffu, lsum, o);
        if (lane == 0) wsum[w] = lsum;
        __syncthreads();
        if (tid == 0) {
            float t = 0.0f;
#pragma unroll
            for (int ww = 0; ww < 8; ww++) t += wsum[ww];
            atomicAdd(&g_sumsq, t);
        }
    }
}

// ---------------- kernel: scalars ----------------------------------------
__global__ void vq_final(float* __restrict__ out) {
    __shared__ float red[256];
    const int tid = threadIdx.x;
    float h = 0.0f;
    for (int i = tid; i < N_CODES; i += 256) {
        float e = (float)g_counts[i] * (1.0f / 65536.0f);
        h -= e * logf(e + 1e-10f);
    }
    red[tid] = h;
    __syncthreads();
    for (int o = 128; o > 0; o >>= 1) {
        if (tid < o) red[tid] += red[tid + o];
        __syncthreads();
    }
    if (tid == 0) {
        out[O_LOSS] = 1.25f * g_sumsq / 4194304.0f;
        out[O_PERP] = expf(red[0]);
    }
}

extern "C" void kernel_launch(void* const* d_in, const int* in_sizes, int n_in,
                              void* d_out, int out_size) {
    const float* z  = (const float*)d_in[0];
    const float* cb = (const float*)d_in[1];
    if (n_in >= 2 && in_sizes[0] == N_CODES * CDIM) {
        z  = (const float*)d_in[1];
        cb = (const float*)d_in[0];
    }
    float* out = (float*)d_out;

    cudaFuncSetAttribute(vq_mma, cudaFuncAttributeMaxDynamicSharedMemorySize,
                         DSMEM_REQ);

    vq_split_z<<<N_TILES, 128>>>(z);
    vq_split_cb<<<64, 128>>>(cb);
    vq_init<<<1, 256>>>();
    vq_mma<<<N_TILES, 256, DSMEM_REQ>>>(cb, out);
    vq_final<<<1, 256>>>(out);
    (void)out_size;
}